// round 7
// baseline (speedup 1.0000x reference)
#include <cuda_runtime.h>
#include <cuda_bf16.h>

// Shapes (fixed): B=16, TE=TD=128, H=256
#define Bsz 16
#define TT 128
#define HH 256
#define MROWS (Bsz*TT)   // 2048

typedef unsigned long long u64;

// Scratch (device globals; no allocation allowed)
__device__ float g_enc[MROWS*HH];   // orthogonalized encoder [B*TE][H]
__device__ float g_was[MROWS*HH];   // enc_ortho @ W_a
__device__ float g_uah[MROWS*HH];   // dec @ U_a

__device__ __forceinline__ float tanh_fast(float x) {
    float y;
    asm("tanh.approx.f32 %0, %1;" : "=f"(y) : "f"(x));
    return y;
}
__device__ __forceinline__ u64 pack2(float lo, float hi) {
    u64 r; asm("mov.b64 %0, {%1, %2};" : "=l"(r) : "f"(lo), "f"(hi)); return r;
}
__device__ __forceinline__ void unpack2(u64 v, float& a, float& b) {
    asm("mov.b64 {%0, %1}, %2;" : "=f"(a), "=f"(b) : "l"(v));
}
// d = a*b + d on packed f32x2 (Blackwell FFMA2)
__device__ __forceinline__ void fma2(u64& d, u64 a, u64 b) {
    asm("fma.rn.f32x2 %0, %1, %2, %0;" : "+l"(d) : "l"(a), "l"(b));
}

// ---------------------------------------------------------------------------
// K1: orthogonalize. out[t] = x[t] - sum_{j<t} x[j]  (elementwise identity of
// the reference formula: x - ((x*s)/(x*x))*x == x - s).
// grid (8 hb, 16 b) = 128 CTAs; block 256 = 32 segs x 8 float4-lanes.
// Each thread: 4 timesteps x 4 h, register-resident (single global read pass).
// ---------------------------------------------------------------------------
__global__ __launch_bounds__(256) void ortho_kernel(const float* __restrict__ enc) {
    int hb = blockIdx.x;             // 0..7  (32 h each)
    int b  = blockIdx.y;             // 0..15
    int tid = threadIdx.x;
    int seg = tid >> 3;              // 0..31 (4 timesteps each)
    int hq  = tid & 7;               // float4 group within 32 h
    int h = hb * 32 + hq * 4;
    int t0 = seg * 4;

    const float4* base = (const float4*)(enc + (size_t)(b * TT + t0) * HH + h);
    float4* obase = (float4*)(g_enc + (size_t)(b * TT + t0) * HH + h);

    float4 x[4];
    #pragma unroll
    for (int t = 0; t < 4; t++) x[t] = base[t * (HH / 4)];

    float4 ps;
    ps.x = x[0].x + x[1].x + x[2].x + x[3].x;
    ps.y = x[0].y + x[1].y + x[2].y + x[3].y;
    ps.z = x[0].z + x[1].z + x[2].z + x[3].z;
    ps.w = x[0].w + x[1].w + x[2].w + x[3].w;

    __shared__ float4 part[32][8];
    part[seg][hq] = ps;
    __syncthreads();

    float4 run = {0.f, 0.f, 0.f, 0.f};
    for (int s = 0; s < seg; s++) {
        float4 p = part[s][hq];
        run.x += p.x; run.y += p.y; run.z += p.z; run.w += p.w;
    }

    #pragma unroll
    for (int t = 0; t < 4; t++) {
        float4 o;
        o.x = x[t].x - run.x;
        o.y = x[t].y - run.y;
        o.z = x[t].z - run.z;
        o.w = x[t].w - run.w;
        obase[t * (HH / 4)] = o;
        run.x += x[t].x; run.y += x[t].y; run.z += x[t].z; run.w += x[t].w;
    }
}

// ---------------------------------------------------------------------------
// K2: two GEMMs [2048,256]@[256,256]. BM=128 BN=64 BK=32, 8x4 microtile with
// f32x2 packed FMA (pairs along M), 256 threads, register prefetch.
// grid (16, 4, 2). z=0: g_enc @ W_a -> g_was ; z=1: dec @ U_a -> g_uah
// ---------------------------------------------------------------------------
#define BMP 132
#define BNP 68
__global__ __launch_bounds__(256) void gemm2_kernel(const float* __restrict__ dec,
                                                    const float* __restrict__ Wa,
                                                    const float* __restrict__ Ua) {
    const float *A, *W;
    float *C;
    if (blockIdx.z == 0) { A = g_enc; W = Wa; C = g_was; }
    else                 { A = dec;   W = Ua; C = g_uah; }

    __shared__ __align__(16) float As[32 * BMP];
    __shared__ __align__(16) float Bs[32 * BNP];

    int tid = threadIdx.x;
    int mblk = blockIdx.x * 128;
    int nblk = blockIdx.y * 64;

    float4 pa[4], pb[2];

    #define LOADT(kt) { \
        _Pragma("unroll") \
        for (int q = 0; q < 4; q++) { int s = tid + q * 256; int m = s >> 3, kq = s & 7; \
            pa[q] = *(const float4*)&A[(mblk + m) * HH + (kt) * 32 + kq * 4]; } \
        _Pragma("unroll") \
        for (int q = 0; q < 2; q++) { int s = tid + q * 256; int k = s >> 4, nq = s & 15; \
            pb[q] = *(const float4*)&W[((kt) * 32 + k) * HH + nblk + nq * 4]; } }

    int tr = tid >> 4, tc = tid & 15;
    int m0 = tr * 8, n0 = tc * 4;
    u64 acc2[4][4] = {};   // 4 m-pairs x 4 n

    LOADT(0);
    for (int kt = 0; kt < 8; kt++) {
        __syncthreads();
        #pragma unroll
        for (int q = 0; q < 4; q++) {
            int s = tid + q * 256; int m = s >> 3, kq = s & 7;
            As[(kq * 4 + 0) * BMP + m] = pa[q].x;
            As[(kq * 4 + 1) * BMP + m] = pa[q].y;
            As[(kq * 4 + 2) * BMP + m] = pa[q].z;
            As[(kq * 4 + 3) * BMP + m] = pa[q].w;
        }
        #pragma unroll
        for (int q = 0; q < 2; q++) {
            int s = tid + q * 256; int k = s >> 4, nq = s & 15;
            *(float4*)&Bs[k * BNP + nq * 4] = pb[q];
        }
        __syncthreads();
        if (kt < 7) LOADT(kt + 1);

        #pragma unroll
        for (int kk = 0; kk < 32; kk++) {
            ulonglong2 aA = *(const ulonglong2*)&As[kk * BMP + m0];
            ulonglong2 aB = *(const ulonglong2*)&As[kk * BMP + m0 + 4];
            float4 bb = *(const float4*)&Bs[kk * BNP + n0];
            u64 am2[4] = {aA.x, aA.y, aB.x, aB.y};
            u64 bn2[4] = {pack2(bb.x, bb.x), pack2(bb.y, bb.y),
                          pack2(bb.z, bb.z), pack2(bb.w, bb.w)};
            #pragma unroll
            for (int i = 0; i < 4; i++)
                #pragma unroll
                for (int j = 0; j < 4; j++)
                    fma2(acc2[i][j], am2[i], bn2[j]);
        }
    }
    #pragma unroll
    for (int i = 0; i < 4; i++) {
        float lo[4], hi[4];
        #pragma unroll
        for (int j = 0; j < 4; j++) unpack2(acc2[i][j], lo[j], hi[j]);
        float4 o0 = {lo[0], lo[1], lo[2], lo[3]};
        float4 o1 = {hi[0], hi[1], hi[2], hi[3]};
        *(float4*)&C[(mblk + m0 + 2 * i) * HH + nblk + n0] = o0;
        *(float4*)&C[(mblk + m0 + 2 * i + 1) * HH + nblk + n0] = o1;
    }
    #undef LOADT
}

// ---------------------------------------------------------------------------
// K3 (fused): energy + softmax + context. grid (8 dblocks, 16 b), block 512.
// was_t stride 136 (8h+e bank map -> 4-way STS conflicts instead of 8-way).
// ---------------------------------------------------------------------------
#define WTP 136
__global__ __launch_bounds__(512) void energy_ctx_kernel(const float* __restrict__ Va,
                                                         float* __restrict__ eo,
                                                         float* __restrict__ co) {
    extern __shared__ float sm3[];
    // phase-1 layout
    float* was_t = sm3;                  // 256*136 = 34816 floats
    float* uah_t = was_t + 256 * WTP;    // 256*20
    float* Vs    = uah_t + 256 * 20;     // 256
    // phase-2 layout (aliases phase-1, valid after the mid-kernel barrier)
    float* Es = sm3;                     // [128 e][256 h] = 32768 floats
    float* Pt = sm3 + 32768;             // [16 d][128 e]  = 2048 floats

    int db = blockIdx.x;
    int b  = blockIdx.y;
    int tid = threadIdx.x;

    for (int idx = tid; idx < TT * HH; idx += 512) {
        int e = idx >> 8, h = idx & 255;
        was_t[h * WTP + e] = g_was[(b * TT + e) * HH + h];
    }
    for (int idx = tid; idx < 16 * HH; idx += 512) {
        int dd = idx >> 8, h = idx & 255;
        uah_t[h * 20 + dd] = g_uah[(b * TT + db * 16 + dd) * HH + h];
    }
    if (tid < 256) Vs[tid] = Va[tid];
    __syncthreads();

    int eg = tid & 31, dg = tid >> 5;    // dg = warp = d-row (0..15)
    int e0 = eg * 4;
    const float* wp = was_t + e0;
    const float* up = uah_t + dg;

    float a0 = 0.f, a1 = 0.f, a2 = 0.f, a3 = 0.f;
    #pragma unroll 4
    for (int h = 0; h < HH; h++) {
        float4 w4 = *(const float4*)(wp + h * WTP);
        float u = up[h * 20];
        float v = Vs[h];
        a0 += v * tanh_fast(u + w4.x);
        a1 += v * tanh_fast(u + w4.y);
        a2 += v * tanh_fast(u + w4.z);
        a3 += v * tanh_fast(u + w4.w);
    }

    // warp softmax over the 128-wide row (4 values per lane)
    float m = fmaxf(fmaxf(a0, a1), fmaxf(a2, a3));
    #pragma unroll
    for (int o = 16; o > 0; o >>= 1) m = fmaxf(m, __shfl_xor_sync(0xffffffffu, m, o));
    float x0 = __expf(a0 - m), x1 = __expf(a1 - m);
    float x2 = __expf(a2 - m), x3 = __expf(a3 - m);
    float ssum = x0 + x1 + x2 + x3;
    #pragma unroll
    for (int o = 16; o > 0; o >>= 1) ssum += __shfl_xor_sync(0xffffffffu, ssum, o);
    float inv = 1.f / ssum;
    float4 p4 = {x0 * inv, x1 * inv, x2 * inv, x3 * inv};
    *(float4*)&eo[(b * TT + db * 16 + dg) * TT + e0] = p4;

    // ---- phase 2: context ----
    __syncthreads();   // all reads of was_t/uah_t complete before aliasing

    // P^T: warp dg writes its row (lane-consecutive -> conflict-free)
    *(float4*)&Pt[dg * 128 + e0] = p4;
    // stage E (overwrites was_t region)
    #pragma unroll
    for (int t = tid; t < (TT * HH) / 4; t += 512) {
        int e = t >> 6, hq = t & 63;
        *(float4*)&Es[e * HH + hq * 4] =
            *(const float4*)&g_enc[(b * TT + e) * HH + hq * 4];
    }
    __syncthreads();

    // block GEMM: C[16,256] = P[16,128] @ E[128,256]
    int mp = tid >> 6, tc = tid & 63;
    int m0 = mp * 2, n0 = tc * 4;
    const float* p0r = Pt + m0 * 128;
    const float* p1r = Pt + (m0 + 1) * 128;
    const float* er  = Es + n0;

    u64 acc2[2][2] = {};   // [m][n-pair]
    #pragma unroll 4
    for (int k = 0; k < 128; k++) {
        float pv0 = p0r[k];              // LDS.32 broadcast
        float pv1 = p1r[k];
        ulonglong2 ev = *(const ulonglong2*)(er + k * HH);   // (n0,n0+1),(n0+2,n0+3)
        u64 pa0 = pack2(pv0, pv0);
        u64 pa1 = pack2(pv1, pv1);
        fma2(acc2[0][0], pa0, ev.x); fma2(acc2[0][1], pa0, ev.y);
        fma2(acc2[1][0], pa1, ev.x); fma2(acc2[1][1], pa1, ev.y);
    }

    #pragma unroll
    for (int i = 0; i < 2; i++) {
        float l0, h0, l1, h1;
        unpack2(acc2[i][0], l0, h0);
        unpack2(acc2[i][1], l1, h1);
        float4 r = {l0, h0, l1, h1};
        *(float4*)&co[(b * TT + db * 16 + m0 + i) * HH + n0] = r;
    }
}

// ---------------------------------------------------------------------------
extern "C" void kernel_launch(void* const* d_in, const int* in_sizes, int n_in,
                              void* d_out, int out_size) {
    const float* enc = (const float*)d_in[0];
    const float* dec = (const float*)d_in[1];
    const float* Wa  = (const float*)d_in[2];
    const float* Ua  = (const float*)d_in[3];
    const float* Va  = (const float*)d_in[4];

    float* co = (float*)d_out;                    // c_outputs [16,128,256]
    float* eo = co + Bsz * TT * HH;               // e_outputs [16,128,128]

    const int SM3 = (256 * WTP + 256 * 20 + 256) * 4;   // 160768 B
    static bool attr_done = false;
    if (!attr_done) {
        cudaFuncSetAttribute(energy_ctx_kernel,
                             cudaFuncAttributeMaxDynamicSharedMemorySize, SM3);
        attr_done = true;
    }

    ortho_kernel<<<dim3(8, 16), 256>>>(enc);
    gemm2_kernel<<<dim3(16, 4, 2), 256>>>(dec, Wa, Ua);
    energy_ctx_kernel<<<dim3(8, 16), 512, SM3>>>(Va, eo, co);
}

// round 8
// speedup vs baseline: 1.4340x; 1.4340x over previous
#include <cuda_runtime.h>
#include <cuda_bf16.h>

// Shapes (fixed): B=16, TE=TD=128, H=256
#define Bsz 16
#define TT 128
#define HH 256
#define MROWS (Bsz*TT)   // 2048

typedef unsigned long long u64;

// Scratch (device globals; no allocation allowed)
__device__ float g_enc[MROWS*HH];    // orthogonalized encoder [B*TE][H]
__device__ float g_wasT[MROWS*HH];   // (enc_ortho @ W_a) TRANSPOSED: [b][h][e]
__device__ float g_uah[MROWS*HH];    // dec @ U_a  (row-major [b*TD+d][h])

__device__ __forceinline__ float tanh_fast(float x) {
    float y;
    asm("tanh.approx.f32 %0, %1;" : "=f"(y) : "f"(x));
    return y;
}
__device__ __forceinline__ u64 pack2(float lo, float hi) {
    u64 r; asm("mov.b64 %0, {%1, %2};" : "=l"(r) : "f"(lo), "f"(hi)); return r;
}
__device__ __forceinline__ void unpack2(u64 v, float& a, float& b) {
    asm("mov.b64 {%0, %1}, %2;" : "=f"(a), "=f"(b) : "l"(v));
}
// d = a*b + d on packed f32x2 (Blackwell FFMA2)
__device__ __forceinline__ void fma2(u64& d, u64 a, u64 b) {
    asm("fma.rn.f32x2 %0, %1, %2, %0;" : "+l"(d) : "l"(a), "l"(b));
}

// ---------------------------------------------------------------------------
// K1: orthogonalize. out[t] = x[t] - sum_{j<t} x[j]  (elementwise identity of
// the reference formula: x - ((x*s)/(x*x))*x == x - s).
// grid (8 hb, 16 b) = 128 CTAs; block 256 = 32 segs x 8 float4-lanes.
// ---------------------------------------------------------------------------
__global__ __launch_bounds__(256) void ortho_kernel(const float* __restrict__ enc) {
    int hb = blockIdx.x;             // 0..7  (32 h each)
    int b  = blockIdx.y;             // 0..15
    int tid = threadIdx.x;
    int seg = tid >> 3;              // 0..31 (4 timesteps each)
    int hq  = tid & 7;               // float4 group within 32 h
    int h = hb * 32 + hq * 4;
    int t0 = seg * 4;

    const float4* base = (const float4*)(enc + (size_t)(b * TT + t0) * HH + h);
    float4* obase = (float4*)(g_enc + (size_t)(b * TT + t0) * HH + h);

    float4 x[4];
    #pragma unroll
    for (int t = 0; t < 4; t++) x[t] = base[t * (HH / 4)];

    float4 ps;
    ps.x = x[0].x + x[1].x + x[2].x + x[3].x;
    ps.y = x[0].y + x[1].y + x[2].y + x[3].y;
    ps.z = x[0].z + x[1].z + x[2].z + x[3].z;
    ps.w = x[0].w + x[1].w + x[2].w + x[3].w;

    __shared__ float4 part[32][8];
    part[seg][hq] = ps;
    __syncthreads();

    float4 run = {0.f, 0.f, 0.f, 0.f};
    for (int s = 0; s < seg; s++) {
        float4 p = part[s][hq];
        run.x += p.x; run.y += p.y; run.z += p.z; run.w += p.w;
    }

    #pragma unroll
    for (int t = 0; t < 4; t++) {
        float4 o;
        o.x = x[t].x - run.x;
        o.y = x[t].y - run.y;
        o.z = x[t].z - run.z;
        o.w = x[t].w - run.w;
        obase[t * (HH / 4)] = o;
        run.x += x[t].x; run.y += x[t].y; run.z += x[t].z; run.w += x[t].w;
    }
}

// ---------------------------------------------------------------------------
// K2: two GEMMs [2048,256]@[256,256]. BM=128 BN=64 BK=32, 8x4 microtile with
// f32x2 packed FMA (pairs along M), 256 threads, register prefetch.
// grid (16, 4, 2).
// z=0: g_enc @ W_a -> g_wasT (TRANSPOSED [b][h][e]); z=1: dec @ U_a -> g_uah.
// ---------------------------------------------------------------------------
#define BMP 132
#define BNP 68
__global__ __launch_bounds__(256) void gemm2_kernel(const float* __restrict__ dec,
                                                    const float* __restrict__ Wa,
                                                    const float* __restrict__ Ua) {
    const float *A, *W;
    if (blockIdx.z == 0) { A = g_enc; W = Wa; }
    else                 { A = dec;   W = Ua; }

    __shared__ __align__(16) float As[32 * BMP];
    __shared__ __align__(16) float Bs[32 * BNP];

    int tid = threadIdx.x;
    int mblk = blockIdx.x * 128;
    int nblk = blockIdx.y * 64;

    float4 pa[4], pb[2];

    #define LOADT(kt) { \
        _Pragma("unroll") \
        for (int q = 0; q < 4; q++) { int s = tid + q * 256; int m = s >> 3, kq = s & 7; \
            pa[q] = *(const float4*)&A[(mblk + m) * HH + (kt) * 32 + kq * 4]; } \
        _Pragma("unroll") \
        for (int q = 0; q < 2; q++) { int s = tid + q * 256; int k = s >> 4, nq = s & 15; \
            pb[q] = *(const float4*)&W[((kt) * 32 + k) * HH + nblk + nq * 4]; } }

    int tr = tid >> 4, tc = tid & 15;
    int m0 = tr * 8, n0 = tc * 4;
    u64 acc2[4][4] = {};   // 4 m-pairs x 4 n

    LOADT(0);
    for (int kt = 0; kt < 8; kt++) {
        __syncthreads();
        #pragma unroll
        for (int q = 0; q < 4; q++) {
            int s = tid + q * 256; int m = s >> 3, kq = s & 7;
            As[(kq * 4 + 0) * BMP + m] = pa[q].x;
            As[(kq * 4 + 1) * BMP + m] = pa[q].y;
            As[(kq * 4 + 2) * BMP + m] = pa[q].z;
            As[(kq * 4 + 3) * BMP + m] = pa[q].w;
        }
        #pragma unroll
        for (int q = 0; q < 2; q++) {
            int s = tid + q * 256; int k = s >> 4, nq = s & 15;
            *(float4*)&Bs[k * BNP + nq * 4] = pb[q];
        }
        __syncthreads();
        if (kt < 7) LOADT(kt + 1);

        #pragma unroll
        for (int kk = 0; kk < 32; kk++) {
            ulonglong2 aA = *(const ulonglong2*)&As[kk * BMP + m0];
            ulonglong2 aB = *(const ulonglong2*)&As[kk * BMP + m0 + 4];
            float4 bb = *(const float4*)&Bs[kk * BNP + n0];
            u64 am2[4] = {aA.x, aA.y, aB.x, aB.y};
            u64 bn2[4] = {pack2(bb.x, bb.x), pack2(bb.y, bb.y),
                          pack2(bb.z, bb.z), pack2(bb.w, bb.w)};
            #pragma unroll
            for (int i = 0; i < 4; i++)
                #pragma unroll
                for (int j = 0; j < 4; j++)
                    fma2(acc2[i][j], am2[i], bn2[j]);
        }
    }

    if (blockIdx.z == 0) {
        // Transposed store: g_wasT[b][h][e], b = mblk/128 (mblk multiple of 128),
        // e = m - mblk. Thread owns e = m0..m0+7 (contiguous) for 4 h columns.
        int bb = mblk >> 7;
        float* baseT = g_wasT + (size_t)bb * (HH * TT);
        #pragma unroll
        for (int j = 0; j < 4; j++) {
            float v[8];
            #pragma unroll
            for (int i = 0; i < 4; i++) unpack2(acc2[i][j], v[2 * i], v[2 * i + 1]);
            float4 q0 = {v[0], v[1], v[2], v[3]};
            float4 q1 = {v[4], v[5], v[6], v[7]};
            float* col = baseT + (size_t)(nblk + n0 + j) * TT + m0;
            *(float4*)col = q0;
            *(float4*)(col + 4) = q1;
        }
    } else {
        float* C = g_uah;
        #pragma unroll
        for (int i = 0; i < 4; i++) {
            float lo[4], hi[4];
            #pragma unroll
            for (int j = 0; j < 4; j++) unpack2(acc2[i][j], lo[j], hi[j]);
            float4 o0 = {lo[0], lo[1], lo[2], lo[3]};
            float4 o1 = {hi[0], hi[1], hi[2], hi[3]};
            *(float4*)&C[(mblk + m0 + 2 * i) * HH + nblk + n0] = o0;
            *(float4*)&C[(mblk + m0 + 2 * i + 1) * HH + nblk + n0] = o1;
        }
    }
    #undef LOADT
}

// ---------------------------------------------------------------------------
// K3 (fused): energy + softmax + context. grid (8 dblocks, 16 b), block 512.
// was_t staged from g_wasT (already [h][e]) -> coalesced LDG + conflict-free STS.
// ---------------------------------------------------------------------------
#define WTP 132
__global__ __launch_bounds__(512) void energy_ctx_kernel(const float* __restrict__ Va,
                                                         float* __restrict__ eo,
                                                         float* __restrict__ co) {
    extern __shared__ float sm3[];
    // phase-1 layout
    float* was_t = sm3;                  // 256*132 = 33792 floats
    float* uah_t = was_t + 256 * WTP;    // 256*20
    float* Vs    = uah_t + 256 * 20;     // 256
    // phase-2 layout (aliases phase-1, valid after the mid-kernel barrier)
    float* Es = sm3;                     // [128 e][256 h] = 32768 floats
    float* Pt = sm3 + 32768;             // [16 d][128 e]  = 2048 floats

    int db = blockIdx.x;
    int b  = blockIdx.y;
    int tid = threadIdx.x;

    // was_t[h][e] <- g_wasT[b][h][e]: consecutive tid -> consecutive e.
    const float* wsrc = g_wasT + (size_t)b * (HH * TT);
    for (int idx = tid; idx < HH * TT; idx += 512) {
        int h = idx >> 7, e = idx & 127;
        was_t[h * WTP + e] = wsrc[idx];
    }
    for (int idx = tid; idx < 16 * HH; idx += 512) {
        int dd = idx >> 8, h = idx & 255;
        uah_t[h * 20 + dd] = g_uah[(b * TT + db * 16 + dd) * HH + h];
    }
    if (tid < 256) Vs[tid] = Va[tid];
    __syncthreads();

    int eg = tid & 31, dg = tid >> 5;    // dg = warp = d-row (0..15)
    int e0 = eg * 4;
    const float* wp = was_t + e0;
    const float* up = uah_t + dg;

    float a0 = 0.f, a1 = 0.f, a2 = 0.f, a3 = 0.f;
    #pragma unroll 4
    for (int h = 0; h < HH; h++) {
        float4 w4 = *(const float4*)(wp + h * WTP);
        float u = up[h * 20];
        float v = Vs[h];
        a0 += v * tanh_fast(u + w4.x);
        a1 += v * tanh_fast(u + w4.y);
        a2 += v * tanh_fast(u + w4.z);
        a3 += v * tanh_fast(u + w4.w);
    }

    // warp softmax over the 128-wide row (4 values per lane)
    float m = fmaxf(fmaxf(a0, a1), fmaxf(a2, a3));
    #pragma unroll
    for (int o = 16; o > 0; o >>= 1) m = fmaxf(m, __shfl_xor_sync(0xffffffffu, m, o));
    float x0 = __expf(a0 - m), x1 = __expf(a1 - m);
    float x2 = __expf(a2 - m), x3 = __expf(a3 - m);
    float ssum = x0 + x1 + x2 + x3;
    #pragma unroll
    for (int o = 16; o > 0; o >>= 1) ssum += __shfl_xor_sync(0xffffffffu, ssum, o);
    float inv = 1.f / ssum;
    float4 p4 = {x0 * inv, x1 * inv, x2 * inv, x3 * inv};
    *(float4*)&eo[(b * TT + db * 16 + dg) * TT + e0] = p4;

    // ---- phase 2: context ----
    __syncthreads();   // all reads of was_t/uah_t complete before aliasing

    // P^T: warp dg writes its row (lane-consecutive -> conflict-free)
    *(float4*)&Pt[dg * 128 + e0] = p4;
    // stage E (overwrites was_t region)
    #pragma unroll
    for (int t = tid; t < (TT * HH) / 4; t += 512) {
        int e = t >> 6, hq = t & 63;
        *(float4*)&Es[e * HH + hq * 4] =
            *(const float4*)&g_enc[(b * TT + e) * HH + hq * 4];
    }
    __syncthreads();

    // block GEMM: C[16,256] = P[16,128] @ E[128,256]
    int mp = tid >> 6, tc = tid & 63;
    int m0 = mp * 2, n0 = tc * 4;
    const float* p0r = Pt + m0 * 128;
    const float* p1r = Pt + (m0 + 1) * 128;
    const float* er  = Es + n0;

    u64 acc2[2][2] = {};   // [m][n-pair]
    #pragma unroll 4
    for (int k = 0; k < 128; k++) {
        float pv0 = p0r[k];              // LDS.32 broadcast
        float pv1 = p1r[k];
        ulonglong2 ev = *(const ulonglong2*)(er + k * HH);
        u64 pa0 = pack2(pv0, pv0);
        u64 pa1 = pack2(pv1, pv1);
        fma2(acc2[0][0], pa0, ev.x); fma2(acc2[0][1], pa0, ev.y);
        fma2(acc2[1][0], pa1, ev.x); fma2(acc2[1][1], pa1, ev.y);
    }

    #pragma unroll
    for (int i = 0; i < 2; i++) {
        float l0, h0, l1, h1;
        unpack2(acc2[i][0], l0, h0);
        unpack2(acc2[i][1], l1, h1);
        float4 r = {l0, h0, l1, h1};
        *(float4*)&co[(b * TT + db * 16 + m0 + i) * HH + n0] = r;
    }
}

// ---------------------------------------------------------------------------
extern "C" void kernel_launch(void* const* d_in, const int* in_sizes, int n_in,
                              void* d_out, int out_size) {
    const float* enc = (const float*)d_in[0];
    const float* dec = (const float*)d_in[1];
    const float* Wa  = (const float*)d_in[2];
    const float* Ua  = (const float*)d_in[3];
    const float* Va  = (const float*)d_in[4];

    float* co = (float*)d_out;                    // c_outputs [16,128,256]
    float* eo = co + Bsz * TT * HH;               // e_outputs [16,128,128]

    const int SM3 = (256 * WTP + 256 * 20 + 256) * 4;   // 156672 B
    static bool attr_done = false;
    if (!attr_done) {
        cudaFuncSetAttribute(energy_ctx_kernel,
                             cudaFuncAttributeMaxDynamicSharedMemorySize, SM3);
        attr_done = true;
    }

    ortho_kernel<<<dim3(8, 16), 256>>>(enc);
    gemm2_kernel<<<dim3(16, 4, 2), 256>>>(dec, Wa, Ua);
    energy_ctx_kernel<<<dim3(8, 16), 512, SM3>>>(Va, eo, co);
}